// round 5
// baseline (speedup 1.0000x reference)
#include <cuda_runtime.h>
#include <math.h>

#define T_STEPS 512
#define BATCH   64
#define IN_DIM  512
#define RNN_DIM 512

#define N_RNN   128   // rnn CTAs: blockIdx 0..127 (32 jblk x 4 bblk)
#define NTHR    256
#define GRP_SZ  32    // CTAs per bblk group

// gemm tiling: one tile = one t-step (64 rows) x 128 cols
#define BM 64
#define BN 128
#define BK 8
#define N_TILES (T_STEPS * (RNN_DIM / BN))   // 512 * 4 = 2048

// scratch (no device allocs allowed)
__device__ float g_pre[(size_t)T_STEPS * BATCH * RNN_DIM];   // 64MB
__device__ float g_hT[2][RNN_DIM * BATCH];                    // [parity][r][b]
__device__ unsigned long long g_grp[4 * 16];                  // group barrier ctrs
__device__ unsigned int g_pre_rdy[T_STEPS];                   // tiles-done per t

__global__ void init_kernel() {
    g_pre_rdy[threadIdx.x] = 0u;
    if (threadIdx.x < 4) g_grp[threadIdx.x * 16] = 0ULL;
}

// ---------------------------------------------------------------------------
__device__ __forceinline__ void group_barrier(int grp, unsigned long long step)
{
    __syncthreads();
    if (threadIdx.x == 0) {
        __threadfence();
        atomicAdd(&g_grp[grp * 16], 1ULL);     // no-return -> REDG
        volatile unsigned long long* ctr =
            (volatile unsigned long long*)&g_grp[grp * 16];
        unsigned long long need = (unsigned long long)GRP_SZ * step;
        while (*ctr < need) { }
        __threadfence();
    }
    __syncthreads();
}

extern __shared__ float smem_dyn[];

// ---------------------------------------------------------------------------
// GEMM role: one 64x128 tile of pre[t] = X[t] @ Wx + bias, then publish.
// ---------------------------------------------------------------------------
__device__ void gemm_role(int tile,
                          const float* __restrict__ X,
                          const float* __restrict__ W,
                          const float* __restrict__ bias)
{
    float* As = smem_dyn;                // [BK][BM] 2KB
    float* Bs = smem_dyn + BK * BM;      // [BK][BN] 4KB

    const int tid = threadIdx.x;
    const int t  = tile >> 2;            // t-major ordering
    const int bn = tile & 3;

    const float* Aptr = X + (size_t)t * BM * IN_DIM;
    const float* Bptr = W + (size_t)bn * BN;

    const int tm = (tid >> 4) * 4;       // 16 row-groups of 4
    const int tn = (tid & 15) * 8;       // 16 col-groups of 8

    const int a_row = tid >> 1;          // tid<128: rows 0..63
    const int a_kq  = (tid & 1) * 4;
    const int b_k   = tid >> 5;          // 0..7
    const int b_nq  = (tid & 31) * 4;

    float c[4][8];
    #pragma unroll
    for (int i = 0; i < 4; i++)
        #pragma unroll
        for (int j = 0; j < 8; j++)
            c[i][j] = 0.0f;

    for (int k0 = 0; k0 < IN_DIM; k0 += BK) {
        float4 av;
        if (tid < 128)
            av = *(const float4*)(Aptr + (size_t)a_row * IN_DIM + k0 + a_kq);
        float4 bv = *(const float4*)(Bptr + (size_t)(k0 + b_k) * RNN_DIM + b_nq);
        __syncthreads();
        if (tid < 128) {
            As[(a_kq + 0) * BM + a_row] = av.x;
            As[(a_kq + 1) * BM + a_row] = av.y;
            As[(a_kq + 2) * BM + a_row] = av.z;
            As[(a_kq + 3) * BM + a_row] = av.w;
        }
        *(float4*)&Bs[b_k * BN + b_nq] = bv;
        __syncthreads();

        #pragma unroll
        for (int k = 0; k < BK; k++) {
            float ar[4], br[8];
            *(float4*)(ar)     = *(float4*)&As[k * BM + tm];
            *(float4*)(br)     = *(float4*)&Bs[k * BN + tn];
            *(float4*)(br + 4) = *(float4*)&Bs[k * BN + tn + 4];
            #pragma unroll
            for (int i = 0; i < 4; i++)
                #pragma unroll
                for (int j = 0; j < 8; j++)
                    c[i][j] += ar[i] * br[j];
        }
    }

    float4 bb0 = *(const float4*)(bias + bn * BN + tn);
    float4 bb1 = *(const float4*)(bias + bn * BN + tn + 4);
    #pragma unroll
    for (int i = 0; i < 4; i++) {
        size_t row = (size_t)t * BM + tm + i;
        float4 v0, v1;
        v0.x = c[i][0] + bb0.x; v0.y = c[i][1] + bb0.y;
        v0.z = c[i][2] + bb0.z; v0.w = c[i][3] + bb0.w;
        v1.x = c[i][4] + bb1.x; v1.y = c[i][5] + bb1.y;
        v1.z = c[i][6] + bb1.z; v1.w = c[i][7] + bb1.w;
        *(float4*)(g_pre + row * RNN_DIM + bn * BN + tn)     = v0;
        *(float4*)(g_pre + row * RNN_DIM + bn * BN + tn + 4) = v1;
    }

    // publish: all writes visible, then bump per-t counter
    __threadfence();
    __syncthreads();
    if (tid == 0) atomicAdd(&g_pre_rdy[t], 1u);
}

// ---------------------------------------------------------------------------
// RNN role (identical math to R4; adds pre[t] readiness watermark).
// ---------------------------------------------------------------------------
__device__ void rnn_role(const float* __restrict__ W,
                         const float* __restrict__ init_hidden,
                         float* __restrict__ out)
{
    float* ws = smem_dyn;                 // [512][16] Wh slice, 32KB
    float* hs = smem_dyn + RNN_DIM * 16;  // [512][16] h slab, 32KB

    const int tid  = threadIdx.x;
    const int jblk = blockIdx.x & 31;
    const int bblk = blockIdx.x >> 5;
    const int j0 = jblk * 16;
    const int b0 = bblk * 16;

    #pragma unroll
    for (int i = 0; i < 8; i++) {
        int idx = tid + i * NTHR;
        int r = idx >> 2, q = (idx & 3) * 4;
        *(float4*)&ws[r * 16 + q] =
            *(const float4*)(W + (size_t)(IN_DIM + r) * RNN_DIM + j0 + q);
    }

    {
        int b = tid >> 4, j = tid & 15;
        out[(size_t)(b0 + b) * RNN_DIM + j0 + j] = init_hidden[j0 + j];
    }
    if (jblk == 0) {
        int kbase = (tid >> 2) * 8;
        int q = (tid & 3) * 4;
        #pragma unroll
        for (int kk = 0; kk < 8; kk++) {
            int k = kbase + kk;
            float v = init_hidden[k];
            *(float4*)&g_hT[0][k * BATCH + b0 + q] = make_float4(v, v, v, v);
        }
    }
    group_barrier(bblk, 1ULL);

    const int kg = tid >> 4;
    const int tt = tid & 15;
    const int bq = (tt >> 2) * 4;
    const int jq = (tt & 3) * 4;
    const int fb = tid >> 4;
    const int fj = tid & 15;

    int tready = 0;   // per-thread monotone watermark over g_pre_rdy

    for (int t = 0; t < T_STEPS - 1; t++) {
        const float* hsrc = g_hT[t & 1];

        // stage half0 (rows 0..255)
        float4 r0[4];
        #pragma unroll
        for (int i = 0; i < 4; i++) {
            int idx = tid + i * NTHR;
            int r = idx >> 2, q = (idx & 3) * 4;
            r0[i] = *(const float4*)(hsrc + r * BATCH + b0 + q);
        }
        // wait until pre[t] published, then prefetch it
        while (tready <= t) {
            if (*(volatile unsigned int*)&g_pre_rdy[tready] >= 4u) tready++;
        }
        __threadfence();
        float pre = g_pre[((size_t)t * BATCH + b0 + fb) * RNN_DIM + j0 + fj];

        #pragma unroll
        for (int i = 0; i < 4; i++) {
            int idx = tid + i * NTHR;
            int r = idx >> 2, q = (idx & 3) * 4;
            *(float4*)&hs[r * 16 + q] = r0[i];
        }
        __syncthreads();

        // issue half1 loads (rows 256..511), overlap with compute half0
        float4 r1[4];
        #pragma unroll
        for (int i = 0; i < 4; i++) {
            int idx = tid + (i + 4) * NTHR;
            int r = idx >> 2, q = (idx & 3) * 4;
            r1[i] = *(const float4*)(hsrc + r * BATCH + b0 + q);
        }

        float c[4][4];
        #pragma unroll
        for (int i = 0; i < 4; i++)
            #pragma unroll
            for (int j = 0; j < 4; j++)
                c[i][j] = 0.0f;

        #pragma unroll 4
        for (int kk = 0; kk < 16; kk++) {
            int k = kg + (kk << 4);
            float4 hv = *(float4*)&hs[k * 16 + bq];
            float4 wv = *(float4*)&ws[k * 16 + jq];
            c[0][0] += hv.x * wv.x; c[0][1] += hv.x * wv.y;
            c[0][2] += hv.x * wv.z; c[0][3] += hv.x * wv.w;
            c[1][0] += hv.y * wv.x; c[1][1] += hv.y * wv.y;
            c[1][2] += hv.y * wv.z; c[1][3] += hv.y * wv.w;
            c[2][0] += hv.z * wv.x; c[2][1] += hv.z * wv.y;
            c[2][2] += hv.z * wv.z; c[2][3] += hv.z * wv.w;
            c[3][0] += hv.w * wv.x; c[3][1] += hv.w * wv.y;
            c[3][2] += hv.w * wv.z; c[3][3] += hv.w * wv.w;
        }

        #pragma unroll
        for (int i = 0; i < 4; i++) {
            int idx = tid + (i + 4) * NTHR;
            int r = idx >> 2, q = (idx & 3) * 4;
            *(float4*)&hs[r * 16 + q] = r1[i];
        }
        __syncthreads();

        #pragma unroll 4
        for (int kk = 16; kk < 32; kk++) {
            int k = kg + (kk << 4);
            float4 hv = *(float4*)&hs[k * 16 + bq];
            float4 wv = *(float4*)&ws[k * 16 + jq];
            c[0][0] += hv.x * wv.x; c[0][1] += hv.x * wv.y;
            c[0][2] += hv.x * wv.z; c[0][3] += hv.x * wv.w;
            c[1][0] += hv.y * wv.x; c[1][1] += hv.y * wv.y;
            c[1][2] += hv.y * wv.z; c[1][3] += hv.y * wv.w;
            c[2][0] += hv.z * wv.x; c[2][1] += hv.z * wv.y;
            c[2][2] += hv.z * wv.z; c[2][3] += hv.z * wv.w;
            c[3][0] += hv.w * wv.x; c[3][1] += hv.w * wv.y;
            c[3][2] += hv.w * wv.z; c[3][3] += hv.w * wv.w;
        }

        // k-split partials overlay hs rows < 256 (safe: half1 compute reads rows >= 256)
        float* red = hs;
        #pragma unroll
        for (int i = 0; i < 4; i++)
            #pragma unroll
            for (int j = 0; j < 4; j++)
                red[kg * 256 + (bq + i) * 16 + (jq + j)] = c[i][j];
        __syncthreads();

        float s = 0.0f;
        #pragma unroll
        for (int g = 0; g < 16; g++)
            s += red[g * 256 + tid];
        float h = tanhf(s + pre);
        out[((size_t)(t + 1) * BATCH + b0 + fb) * RNN_DIM + j0 + fj] = h;
        g_hT[(t + 1) & 1][(j0 + fj) * BATCH + b0 + fb] = h;

        if (t < T_STEPS - 2)
            group_barrier(bblk, (unsigned long long)(t + 2));
    }
}

// ---------------------------------------------------------------------------
__global__ __launch_bounds__(NTHR, 2) void fused_kernel(
    const float* __restrict__ X,
    const float* __restrict__ W,
    const float* __restrict__ bias,
    const float* __restrict__ init_hidden,
    float* __restrict__ out)
{
    if (blockIdx.x < N_RNN) {
        rnn_role(W, init_hidden, out);
    } else {
        gemm_role(blockIdx.x - N_RNN, X, W, bias);
    }
}

// ---------------------------------------------------------------------------
extern "C" void kernel_launch(void* const* d_in, const int* in_sizes, int n_in,
                              void* d_out, int out_size)
{
    const float* X    = (const float*)d_in[0];  // [T, B, IN_DIM]
    const float* W    = (const float*)d_in[1];  // [IN_DIM + RNN_DIM, RNN_DIM]
    const float* bias = (const float*)d_in[2];  // [RNN_DIM]
    const float* h0   = (const float*)d_in[3];  // [RNN_DIM]
    float* out = (float*)d_out;                 // [T, B, RNN_DIM]

    cudaFuncSetAttribute(fused_kernel,
                         cudaFuncAttributeMaxDynamicSharedMemorySize, 65536);

    init_kernel<<<1, T_STEPS>>>();
    fused_kernel<<<N_RNN + N_TILES, NTHR, 65536>>>(X, W, bias, h0, out);
}

// round 6
// speedup vs baseline: 1.0558x; 1.0558x over previous
#include <cuda_runtime.h>
#include <math.h>

#define T_STEPS 512
#define BATCH   64
#define IN_DIM  512
#define RNN_DIM 512

#define N_RNN   128   // 32 jblk x 4 bblk
#define NTHR    256

// scratch (no device allocs allowed)
__device__ float g_pre[(size_t)T_STEPS * BATCH * RNN_DIM];   // 64MB
__device__ float g_hT[4][RNN_DIM * BATCH];                    // 4-slot ring, [slot][r][b]
__device__ unsigned int g_hflag[N_RNN * 32];                  // per (bblk,jblk), 128B apart

#define FLAG(bblk, q) g_hflag[(((bblk) << 5) + (q)) << 5]

// ---------------------------------------------------------------------------
// Phase 1: pre = X @ Wx + bias. 128x128x8 register-tiled fp32 GEMM (proven R4).
// Block (0,0) also resets the h-flags (stream-ordered vs prior rnn -> safe).
// ---------------------------------------------------------------------------
#define BM 128
#define BN 128
#define BK 8

__global__ __launch_bounds__(256) void gemm_pre_kernel(
    const float* __restrict__ X,
    const float* __restrict__ W,
    const float* __restrict__ bias)
{
    if (blockIdx.x == 0 && blockIdx.y == 0 && threadIdx.x < N_RNN)
        g_hflag[threadIdx.x << 5] = 0u;

    __shared__ float As[BK][BM];
    __shared__ float Bs[BK][BN];

    const int tid = threadIdx.x;
    const int bm = blockIdx.x;
    const int bn = blockIdx.y;

    const float* Aptr = X + (size_t)bm * BM * IN_DIM;
    const float* Bptr = W + (size_t)bn * BN;

    const int tm = (tid / 16) * 8;
    const int tn = (tid % 16) * 8;

    const int a_row = tid >> 1;
    const int a_kq  = (tid & 1) * 4;
    const int b_k   = tid >> 5;
    const int b_nq  = (tid & 31) * 4;

    float c[8][8];
    #pragma unroll
    for (int i = 0; i < 8; i++)
        #pragma unroll
        for (int j = 0; j < 8; j++)
            c[i][j] = 0.0f;

    for (int k0 = 0; k0 < IN_DIM; k0 += BK) {
        float4 av = *(const float4*)(Aptr + (size_t)a_row * IN_DIM + k0 + a_kq);
        float4 bv = *(const float4*)(Bptr + (size_t)(k0 + b_k) * RNN_DIM + b_nq);
        __syncthreads();
        As[a_kq + 0][a_row] = av.x;
        As[a_kq + 1][a_row] = av.y;
        As[a_kq + 2][a_row] = av.z;
        As[a_kq + 3][a_row] = av.w;
        *(float4*)&Bs[b_k][b_nq] = bv;
        __syncthreads();

        #pragma unroll
        for (int k = 0; k < BK; k++) {
            float ar[8], br[8];
            *(float4*)(ar)     = *(float4*)&As[k][tm];
            *(float4*)(ar + 4) = *(float4*)&As[k][tm + 4];
            *(float4*)(br)     = *(float4*)&Bs[k][tn];
            *(float4*)(br + 4) = *(float4*)&Bs[k][tn + 4];
            #pragma unroll
            for (int i = 0; i < 8; i++)
                #pragma unroll
                for (int j = 0; j < 8; j++)
                    c[i][j] += ar[i] * br[j];
        }
    }

    float4 bb0 = *(const float4*)(bias + bn * BN + tn);
    float4 bb1 = *(const float4*)(bias + bn * BN + tn + 4);
    #pragma unroll
    for (int i = 0; i < 8; i++) {
        size_t row = (size_t)bm * BM + tm + i;
        float4 v0, v1;
        v0.x = c[i][0] + bb0.x; v0.y = c[i][1] + bb0.y;
        v0.z = c[i][2] + bb0.z; v0.w = c[i][3] + bb0.w;
        v1.x = c[i][4] + bb1.x; v1.y = c[i][5] + bb1.y;
        v1.z = c[i][6] + bb1.z; v1.w = c[i][7] + bb1.w;
        *(float4*)(g_pre + row * RNN_DIM + bn * BN + tn)     = v0;
        *(float4*)(g_pre + row * RNN_DIM + bn * BN + tn + 4) = v1;
    }
}

// ---------------------------------------------------------------------------
// Phase 2: persistent RNN, barrier-free producer/consumer tile dataflow.
// CTA (jblk,bblk): produces h tile (16 j-cols x 16 b) each step, consumes
// all 32 tiles of its chain. Warp w consumes tiles 4w..4w+3 (k in [64w,64w+64)).
// 4-deep h ring; consume-condition subsumes the write hazard (see header).
// ---------------------------------------------------------------------------
extern __shared__ float smem_dyn[];

__global__ __launch_bounds__(NTHR) void rnn_seq_kernel(
    const float* __restrict__ W,
    const float* __restrict__ init_hidden,
    float* __restrict__ out)
{
    float* ws = smem_dyn;                 // [512][16] Wh slice, 32KB
    float* hs = smem_dyn + RNN_DIM * 16;  // [512][16] h slab, 32KB (rows<256 = red)

    const int tid  = threadIdx.x;
    const int lane = tid & 31;
    const int wid  = tid >> 5;            // 0..7
    const int jblk = blockIdx.x & 31;
    const int bblk = blockIdx.x >> 5;
    const int j0 = jblk * 16;
    const int b0 = bblk * 16;

    // Wh slice (rows 512..1023 of W, cols j0..j0+15), loaded once
    #pragma unroll
    for (int i = 0; i < 8; i++) {
        int idx = tid + i * NTHR;
        int r = idx >> 2, q = (idx & 3) * 4;
        *(float4*)&ws[r * 16 + q] =
            *(const float4*)(W + (size_t)(IN_DIM + r) * RNN_DIM + j0 + q);
    }

    // out[0] tile = broadcast init_hidden
    {
        int b = tid >> 4, j = tid & 15;
        out[(size_t)(b0 + b) * RNN_DIM + j0 + j] = init_hidden[j0 + j];
    }
    // publish h(0) tile: g_hT[0][j0+r][b0..b0+15] = h0[j0+r]
    if (tid < 64) {
        int r = tid >> 2, c4 = (tid & 3) * 4;
        float v = init_hidden[j0 + r];
        *(float4*)&g_hT[0][(j0 + r) * BATCH + b0 + c4] = make_float4(v, v, v, v);
    }
    __threadfence();
    __syncthreads();
    if (tid == 0)
        *(volatile unsigned int*)&FLAG(bblk, jblk) = 1u;

    const int kg = tid >> 4;              // 0..15, k in [32*kg, 32*kg+32)
    const int tt = tid & 15;
    const int bq = (tt >> 2) * 4;
    const int jq = (tt & 3) * 4;
    const int fb = tid >> 4;              // epilogue b
    const int fj = tid & 15;              // epilogue j

    volatile unsigned int* myflag =
        (volatile unsigned int*)&FLAG(bblk, 4 * wid + (lane & 3));

    for (int t = 0; t < T_STEPS - 1; t++) {
        const float* hbase = g_hT[t & 3];

        // prefetch pre[t] (independent of h flags)
        float pre = g_pre[((size_t)t * BATCH + b0 + fb) * RNN_DIM + j0 + fj];

        // warp-local spin: tiles 4w..4w+3 ready?
        unsigned int need = (unsigned int)(t + 1);
        while (!__all_sync(0xffffffffu, *myflag >= need)) { }
        __threadfence();

        // stage rows [64*wid, 64*wid+64) of h(t) into smem
        #pragma unroll
        for (int i = 0; i < 8; i++) {
            int idx = lane + 32 * i;               // 0..255
            int r = 64 * wid + (idx >> 2);
            int c4 = (idx & 3) * 4;
            *(float4*)&hs[r * 16 + c4] =
                *(const float4*)(hbase + r * BATCH + b0 + c4);
        }
        __syncwarp();

        float c[4][4];
        #pragma unroll
        for (int i = 0; i < 4; i++)
            #pragma unroll
            for (int j = 0; j < 4; j++)
                c[i][j] = 0.0f;

        #pragma unroll 4
        for (int kk = 0; kk < 32; kk++) {
            int k = 32 * kg + kk;
            float4 hv = *(float4*)&hs[k * 16 + bq];
            float4 wv = *(float4*)&ws[k * 16 + jq];
            c[0][0] += hv.x * wv.x; c[0][1] += hv.x * wv.y;
            c[0][2] += hv.x * wv.z; c[0][3] += hv.x * wv.w;
            c[1][0] += hv.y * wv.x; c[1][1] += hv.y * wv.y;
            c[1][2] += hv.y * wv.z; c[1][3] += hv.y * wv.w;
            c[2][0] += hv.z * wv.x; c[2][1] += hv.z * wv.y;
            c[2][2] += hv.z * wv.z; c[2][3] += hv.z * wv.w;
            c[3][0] += hv.w * wv.x; c[3][1] += hv.w * wv.y;
            c[3][2] += hv.w * wv.z; c[3][3] += hv.w * wv.w;
        }

        __syncthreads();   // all warps done reading hs
        float* red = hs;   // overlay rows < 256
        #pragma unroll
        for (int i = 0; i < 4; i++)
            #pragma unroll
            for (int j = 0; j < 4; j++)
                red[kg * 256 + (bq + i) * 16 + (jq + j)] = c[i][j];
        __syncthreads();

        float s = 0.0f;
        #pragma unroll
        for (int g = 0; g < 16; g++)
            s += red[g * 256 + tid];               // conflict-free
        float h = tanhf(s + pre);
        out[((size_t)(t + 1) * BATCH + b0 + fb) * RNN_DIM + j0 + fj] = h;

        if (t < T_STEPS - 2) {
            g_hT[(t + 1) & 3][(j0 + fj) * BATCH + b0 + fb] = h;
            __threadfence();
            __syncthreads();   // all tile stores done + red consumed
            if (tid == 0)
                *(volatile unsigned int*)&FLAG(bblk, jblk) = (unsigned int)(t + 2);
        }
    }
}

// ---------------------------------------------------------------------------
extern "C" void kernel_launch(void* const* d_in, const int* in_sizes, int n_in,
                              void* d_out, int out_size)
{
    const float* X    = (const float*)d_in[0];  // [T, B, IN_DIM]
    const float* W    = (const float*)d_in[1];  // [IN_DIM + RNN_DIM, RNN_DIM]
    const float* bias = (const float*)d_in[2];  // [RNN_DIM]
    const float* h0   = (const float*)d_in[3];  // [RNN_DIM]
    float* out = (float*)d_out;                 // [T, B, RNN_DIM]

    cudaFuncSetAttribute(rnn_seq_kernel,
                         cudaFuncAttributeMaxDynamicSharedMemorySize, 65536);

    dim3 g1((T_STEPS * BATCH) / BM, RNN_DIM / BN);  // (256, 4)
    gemm_pre_kernel<<<g1, 256>>>(X, W, bias);

    rnn_seq_kernel<<<N_RNN, NTHR, 65536>>>(W, h0, out);
}